// round 10
// baseline (speedup 1.0000x reference)
#include <cuda_runtime.h>
#include <cuda_bf16.h>

// CrossNetwork (DCN-v1): x_{l+1} = input * (x_l . w_l) + x_l + b_l, L=6.
//
// Closed form: x_l = alpha_l*input + y_l,  y_l = sum_{j<l} b_j,
//   p_l = input.w_l, q_l = y_l.w_l,  alpha_{l+1} = alpha_l*(1+p_l)+q_l,
//   out = alpha_L*input + y_L.
// One HBM read + one HBM write of [B,D] (128 MB).
//
// Round 10: warp-autonomous mainloop. Each global warp statically owns rows
// {wg, wg+NW, ...} (6-7 rows). Double-buffered register pipeline: next row's
// 8x LDG.128 are in flight while the current row is dotted/reduced/stored.
// No barriers or atomics after the per-CTA W/y/q preamble.

#define D 1024
#define L 6
#define NTHREADS 256
#define D4 (D / 4)          // 256 float4 per row
#define GRID_CTAS 296       // 148 SMs * 2 resident CTAs

__global__ __launch_bounds__(NTHREADS, 2)
void crossnet_kernel(const float* __restrict__ input,
                     const float* __restrict__ Wg,
                     const float* __restrict__ bg,
                     float* __restrict__ out,
                     int B, int nwarps)
{
    __shared__ float4 w_s[L * D4];   // 24 KB: full W
    __shared__ float4 y_s[D4];       // 4 KB: y_L = sum_l b_l
    __shared__ float  q_s[L];        // 6 scalars

    const int tid  = threadIdx.x;
    const int lane = tid & 31;
    const int warp = tid >> 5;

    if (tid < L) q_s[tid] = 0.0f;

    // ---- one-time preamble: W -> smem ----
    const float4* W4 = reinterpret_cast<const float4*>(Wg);
    const float4* B4 = reinterpret_cast<const float4*>(bg);
#pragma unroll
    for (int i = 0; i < L; i++)
        w_s[i * D4 + tid] = W4[i * D4 + tid];
    __syncthreads();

    // ---- one-time: y_L and q_l (redundant per CTA; cheap) ----
    {
        float4 y = make_float4(0.f, 0.f, 0.f, 0.f);
        float ql[L];
#pragma unroll
        for (int l = 0; l < L; l++) {
            float4 w  = w_s[l * D4 + tid];
            float4 bb = B4[l * D4 + tid];
            ql[l] = y.x * w.x + y.y * w.y + y.z * w.z + y.w * w.w;
            y.x += bb.x; y.y += bb.y; y.z += bb.z; y.w += bb.w;
        }
        y_s[tid] = y;
#pragma unroll
        for (int l = 0; l < L; l++) {
            float v = ql[l];
#pragma unroll
            for (int o = 16; o > 0; o >>= 1)
                v += __shfl_xor_sync(0xffffffffu, v, o);
            if (lane == 0) atomicAdd(&q_s[l], v);
        }
    }
    __syncthreads();   // w_s, y_s, q_s final; no barriers after this point

    const int wg = blockIdx.x * (NTHREADS / 32) + warp;   // global warp id

    const float4* inp  = reinterpret_cast<const float4*>(input);
    float4*       outp = reinterpret_cast<float4*>(out);

    // process one row held in buf[8]; row index r
#define PROCESS_ROW(buf, r)                                                  \
    {                                                                        \
        float acc[L];                                                        \
        _Pragma("unroll")                                                    \
        for (int l = 0; l < L; l++) acc[l] = 0.f;                            \
        _Pragma("unroll")                                                    \
        for (int k = 0; k < 8; k++) {                                        \
            _Pragma("unroll")                                                \
            for (int l = 0; l < L; l++) {                                    \
                float4 w = w_s[l * D4 + lane + 32 * k];                      \
                acc[l] = fmaf(buf[k].x, w.x, acc[l]);                        \
                acc[l] = fmaf(buf[k].y, w.y, acc[l]);                        \
                acc[l] = fmaf(buf[k].z, w.z, acc[l]);                        \
                acc[l] = fmaf(buf[k].w, w.w, acc[l]);                        \
            }                                                                \
        }                                                                    \
        _Pragma("unroll")                                                    \
        for (int l = 0; l < L; l++) {                                        \
            _Pragma("unroll")                                                \
            for (int o = 16; o > 0; o >>= 1)                                 \
                acc[l] += __shfl_xor_sync(0xffffffffu, acc[l], o);           \
        }                                                                    \
        float a = 1.0f;                                                      \
        _Pragma("unroll")                                                    \
        for (int l = 0; l < L; l++)                                          \
            a = fmaf(a, acc[l], a) + q_s[l];                                 \
        float4* op = outp + (size_t)(r) * D4;                                \
        _Pragma("unroll")                                                    \
        for (int k = 0; k < 8; k++) {                                        \
            float4 y = y_s[lane + 32 * k];                                   \
            float4 rr;                                                       \
            rr.x = fmaf(a, buf[k].x, y.x);                                   \
            rr.y = fmaf(a, buf[k].y, y.y);                                   \
            rr.z = fmaf(a, buf[k].z, y.z);                                   \
            rr.w = fmaf(a, buf[k].w, y.w);                                   \
            op[lane + 32 * k] = rr;                                          \
        }                                                                    \
    }

#define LOAD_ROW(buf, r)                                                     \
    {                                                                        \
        const float4* ip = inp + (size_t)(r) * D4;                           \
        _Pragma("unroll")                                                    \
        for (int k = 0; k < 8; k++) buf[k] = ip[lane + 32 * k];              \
    }

    float4 bufA[8], bufB[8];

    int r = wg;
    if (r < B) {
        LOAD_ROW(bufA, r)                 // first row's loads in flight
        for (;;) {
            int rn = r + nwarps;
            if (rn < B) LOAD_ROW(bufB, rn)    // prefetch next (independent)
            PROCESS_ROW(bufA, r)              // overlaps with bufB loads
            r = rn;
            if (r >= B) break;

            rn = r + nwarps;
            if (rn < B) LOAD_ROW(bufA, rn)
            PROCESS_ROW(bufB, r)
            r = rn;
            if (r >= B) break;
        }
    }
#undef PROCESS_ROW
#undef LOAD_ROW
}

extern "C" void kernel_launch(void* const* d_in, const int* in_sizes, int n_in,
                              void* d_out, int out_size)
{
    const float* input = (const float*)d_in[0];
    const float* W     = (const float*)d_in[1];
    const float* b     = (const float*)d_in[2];
    float* out         = (float*)d_out;

    const int B      = in_sizes[0] / D;                          // 16384
    int grid         = GRID_CTAS;                                // 296
    const int maxg   = (B + (NTHREADS / 32) - 1) / (NTHREADS / 32);
    if (grid > maxg) grid = maxg;
    const int nwarps = grid * (NTHREADS / 32);                   // 2368

    crossnet_kernel<<<grid, NTHREADS>>>(input, W, b, out, B, nwarps);
}

// round 11
// speedup vs baseline: 3.7434x; 3.7434x over previous
#include <cuda_runtime.h>
#include <cuda_bf16.h>

// CrossNetwork (DCN-v1): x_{l+1} = input * (x_l . w_l) + x_l + b_l, L=6.
//
// Closed form: x_l = alpha_l*input + y_l,  y_l = sum_{j<l} b_j,
//   p_l = input.w_l, q_l = y_l.w_l,  alpha_{l+1} = alpha_l*(1+p_l)+q_l,
//   out = alpha_L*input + y_L.
// One HBM read + one HBM write of [B,D] (128 MB).
//
// Round 11: R7 compute core (2 rows/warp register-resident, scalar FMA)
// but WARP-AUTONOMOUS scheduling: each warp pops 2-row pairs off a global
// atomic counter. Zero barriers in the mainloop -> the SMSP arbiter
// interleaves one warp's load stall with another's compute.

#define D 1024
#define L 6
#define NTHREADS 256
#define D4 (D / 4)          // 256 float4 per row
#define GRID_CTAS 296       // 148 SMs * 2 resident CTAs

__device__ unsigned int g_pair_ctr = 0;
__device__ unsigned int g_done_ctr = 0;

__global__ __launch_bounds__(NTHREADS, 2)
void crossnet_kernel(const float* __restrict__ input,
                     const float* __restrict__ Wg,
                     const float* __restrict__ bg,
                     float* __restrict__ out,
                     int B, int npairs, int totalwarps)
{
    __shared__ float4 w_s[L * D4];   // 24 KB: full W
    __shared__ float4 y_s[D4];       // 4 KB: y_L = sum_l b_l
    __shared__ float  q_s[L];        // 6 scalars

    const int tid  = threadIdx.x;
    const int lane = tid & 31;

    if (tid < L) q_s[tid] = 0.0f;

    // ---- one-time preamble: W -> smem ----
    const float4* W4 = reinterpret_cast<const float4*>(Wg);
    const float4* B4 = reinterpret_cast<const float4*>(bg);
#pragma unroll
    for (int i = 0; i < L; i++)
        w_s[i * D4 + tid] = W4[i * D4 + tid];
    __syncthreads();

    // ---- one-time: y_L and q_l (redundant per CTA; cheap) ----
    {
        float4 y = make_float4(0.f, 0.f, 0.f, 0.f);
        float ql[L];
#pragma unroll
        for (int l = 0; l < L; l++) {
            float4 w  = w_s[l * D4 + tid];
            float4 bb = B4[l * D4 + tid];
            ql[l] = y.x * w.x + y.y * w.y + y.z * w.z + y.w * w.w;
            y.x += bb.x; y.y += bb.y; y.z += bb.z; y.w += bb.w;
        }
        y_s[tid] = y;
#pragma unroll
        for (int l = 0; l < L; l++) {
            float v = ql[l];
#pragma unroll
            for (int o = 16; o > 0; o >>= 1)
                v += __shfl_xor_sync(0xffffffffu, v, o);
            if (lane == 0) atomicAdd(&q_s[l], v);
        }
    }
    __syncthreads();   // w_s, y_s, q_s final; NO barriers after this point

    const float4* inp  = reinterpret_cast<const float4*>(input);
    float4*       outp = reinterpret_cast<float4*>(out);

    // ---- warp-autonomous mainloop: pop 2-row pairs ----
    for (;;) {
        unsigned int v = 0;
        if (lane == 0) v = atomicAdd(&g_pair_ctr, 1u);
        v = __shfl_sync(0xffffffffu, v, 0);
        if (v >= (unsigned int)npairs) break;

        const int row0 = 2 * (int)v;
        const bool r1ok = (row0 + 1 < B);

        const float4* in0p = inp + (size_t)row0 * D4;
        const float4* in1p = in0p + D4;

        // register-resident input (read HBM exactly once)
        float4 in0[8], in1[8];
#pragma unroll
        for (int k = 0; k < 8; k++) {
            in0[k] = in0p[lane + 32 * k];
            in1[k] = r1ok ? in1p[lane + 32 * k] : make_float4(0.f, 0.f, 0.f, 0.f);
        }

        float acc0[L], acc1[L];
#pragma unroll
        for (int l = 0; l < L; l++) { acc0[l] = 0.f; acc1[l] = 0.f; }

#pragma unroll
        for (int k = 0; k < 8; k++) {
#pragma unroll
            for (int l = 0; l < L; l++) {
                float4 w = w_s[l * D4 + lane + 32 * k];
                acc0[l] = fmaf(in0[k].x, w.x, acc0[l]);
                acc0[l] = fmaf(in0[k].y, w.y, acc0[l]);
                acc0[l] = fmaf(in0[k].z, w.z, acc0[l]);
                acc0[l] = fmaf(in0[k].w, w.w, acc0[l]);
                acc1[l] = fmaf(in1[k].x, w.x, acc1[l]);
                acc1[l] = fmaf(in1[k].y, w.y, acc1[l]);
                acc1[l] = fmaf(in1[k].z, w.z, acc1[l]);
                acc1[l] = fmaf(in1[k].w, w.w, acc1[l]);
            }
        }

        // butterfly warp reductions -> every lane holds full p_l
#pragma unroll
        for (int l = 0; l < L; l++) {
#pragma unroll
            for (int o = 16; o > 0; o >>= 1) {
                acc0[l] += __shfl_xor_sync(0xffffffffu, acc0[l], o);
                acc1[l] += __shfl_xor_sync(0xffffffffu, acc1[l], o);
            }
        }

        // scalar recurrence: alpha = alpha*(1+p) + q
        float a0 = 1.0f, a1 = 1.0f;
#pragma unroll
        for (int l = 0; l < L; l++) {
            float q = q_s[l];
            a0 = fmaf(a0, acc0[l], a0) + q;
            a1 = fmaf(a1, acc1[l], a1) + q;
        }

        // epilogue: out = alpha * input + y_L (input from registers)
        float4* o0 = outp + (size_t)row0 * D4;
        float4* o1 = o0 + D4;
#pragma unroll
        for (int k = 0; k < 8; k++) {
            float4 y = y_s[lane + 32 * k];
            float4 r0;
            r0.x = fmaf(a0, in0[k].x, y.x);
            r0.y = fmaf(a0, in0[k].y, y.y);
            r0.z = fmaf(a0, in0[k].z, y.z);
            r0.w = fmaf(a0, in0[k].w, y.w);
            o0[lane + 32 * k] = r0;
            if (r1ok) {
                float4 r1;
                r1.x = fmaf(a1, in1[k].x, y.x);
                r1.y = fmaf(a1, in1[k].y, y.y);
                r1.z = fmaf(a1, in1[k].z, y.z);
                r1.w = fmaf(a1, in1[k].w, y.w);
                o1[lane + 32 * k] = r1;
            }
        }
    }

    // ---- reset counters for next graph replay (last warp out) ----
    if (lane == 0) {
        __threadfence();
        unsigned int d = atomicAdd(&g_done_ctr, 1u);
        if (d == (unsigned int)totalwarps - 1u) {
            atomicExch(&g_pair_ctr, 0u);
            atomicExch(&g_done_ctr, 0u);
        }
    }
}

extern "C" void kernel_launch(void* const* d_in, const int* in_sizes, int n_in,
                              void* d_out, int out_size)
{
    const float* input = (const float*)d_in[0];
    const float* W     = (const float*)d_in[1];
    const float* b     = (const float*)d_in[2];
    float* out         = (float*)d_out;

    const int B      = in_sizes[0] / D;          // 16384
    const int npairs = (B + 1) / 2;              // 8192
    int grid         = GRID_CTAS;                // 296
    const int maxg   = (npairs + (NTHREADS / 32) - 1) / (NTHREADS / 32);
    if (grid > maxg) grid = maxg;
    const int totalwarps = grid * (NTHREADS / 32);   // 2368

    crossnet_kernel<<<grid, NTHREADS>>>(input, W, b, out, B, npairs, totalwarps);
}